// round 4
// baseline (speedup 1.0000x reference)
#include <cuda_runtime.h>
#include <cuda_bf16.h>
#include <cstdint>

#define BS_  8
#define N_   4096
#define B_   8
#define R_   64
#define D_   256

#define MTILE   128
#define THREADS 256
#define ROWB    528        // bytes per smem row: 264 bf16 (256 data + 8 pad)

// ---- smem layout (bytes) ----
#define SMO_AHI  0                        // q hi  [128][264] bf16
#define SMO_ALO  (128*ROWB)               // q lo
#define SMO_BHI  (2*128*ROWB)             // K/V hi [64][264]  (also RED group0: 128x264B fp32)
#define SMO_BLO  (SMO_BHI + 64*ROWB)      // K/V lo            (also RED group1)
#define SMO_PART (SMO_BLO + 64*ROWB)      // 256 floats ssq partials
#define SMO_INV  (SMO_PART + 1024)        // 128 floats
#define SMO_SA   (SMO_INV + 512)          // 64 floats pm_a
#define SMEM_TOTAL (SMO_SA + 256)         // 204544 B
#define REDSZ    33792                    // 128 rows * 264 B

__device__ __forceinline__ uint32_t smem_u32(const void* p) {
    uint32_t a;
    asm("{ .reg .u64 t; cvta.to.shared.u64 t, %1; cvt.u32.u64 %0, t; }" : "=r"(a) : "l"(p));
    return a;
}
__device__ __forceinline__ void ldsm4(uint32_t* r, uint32_t addr) {
    asm volatile("ldmatrix.sync.aligned.m8n8.x4.shared.b16 {%0,%1,%2,%3}, [%4];"
                 : "=r"(r[0]), "=r"(r[1]), "=r"(r[2]), "=r"(r[3]) : "r"(addr));
}
__device__ __forceinline__ void ldsm4t(uint32_t* r, uint32_t addr) {
    asm volatile("ldmatrix.sync.aligned.m8n8.x4.trans.shared.b16 {%0,%1,%2,%3}, [%4];"
                 : "=r"(r[0]), "=r"(r[1]), "=r"(r[2]), "=r"(r[3]) : "r"(addr));
}
__device__ __forceinline__ void mma16816(float* c, const uint32_t* a, const uint32_t* b) {
    asm volatile("mma.sync.aligned.m16n8k16.row.col.f32.bf16.bf16.f32 "
                 "{%0,%1,%2,%3}, {%4,%5,%6,%7}, {%8,%9}, {%0,%1,%2,%3};"
                 : "+f"(c[0]), "+f"(c[1]), "+f"(c[2]), "+f"(c[3])
                 : "r"(a[0]), "r"(a[1]), "r"(a[2]), "r"(a[3]), "r"(b[0]), "r"(b[1]));
}
__device__ __forceinline__ uint32_t packbf(float x, float y) {
    __nv_bfloat162 h = __floats2bfloat162_rn(x, y);
    return *(uint32_t*)&h;
}
__device__ __forceinline__ void split4(float4 v, uint2& hi, uint2& lo) {
    __nv_bfloat16 hx = __float2bfloat16_rn(v.x), hy = __float2bfloat16_rn(v.y);
    __nv_bfloat16 hz = __float2bfloat16_rn(v.z), hw = __float2bfloat16_rn(v.w);
    hi.x = (uint32_t)__bfloat16_as_ushort(hx) | ((uint32_t)__bfloat16_as_ushort(hy) << 16);
    hi.y = (uint32_t)__bfloat16_as_ushort(hz) | ((uint32_t)__bfloat16_as_ushort(hw) << 16);
    lo.x = packbf(v.x - __bfloat162float(hx), v.y - __bfloat162float(hy));
    lo.y = packbf(v.z - __bfloat162float(hz), v.w - __bfloat162float(hw));
}

__global__ __launch_bounds__(THREADS, 1)
void ProceduralMemory_81535659147884_kernel(
    const float* __restrict__ q,
    const float* __restrict__ pm_K,
    const float* __restrict__ pm_V,
    const float* __restrict__ pm_a,
    float* __restrict__ out)
{
    extern __shared__ char smc[];
    const uint32_t smb = smem_u32(smc);

    const int tid  = threadIdx.x;
    const int wid  = tid >> 5;
    const int lane = tid & 31;

    const int pair = blockIdx.x >> 5;
    const int tile = blockIdx.x & 31;
    const int s = pair >> 3, b = pair & 7;
    const int n0 = tile * MTILE;

    float* partS = (float*)(smc + SMO_PART);
    float* invS  = (float*)(smc + SMO_INV);
    float* saS   = (float*)(smc + SMO_SA);

    // ---- Load + split q tile [128,256]: ssq partials + bf16 hi/lo to smem ----
    {
        const int h  = wid & 1;
        const int wr = wid >> 1;
        const int f4 = h * 32 + lane;
        const size_t base4 = ((size_t)(s * N_ + n0) * B_ + b) * (D_ / 4);
        const float4* qg = (const float4*)q;
        #pragma unroll 4
        for (int k = 0; k < 32; ++k) {
            int m = 4 * k + wr;
            float4 v = qg[base4 + (size_t)m * (B_ * D_ / 4) + f4];
            float ss = v.x * v.x + v.y * v.y + v.z * v.z + v.w * v.w;
            #pragma unroll
            for (int o = 16; o; o >>= 1) ss += __shfl_xor_sync(0xFFFFFFFFu, ss, o);
            if (lane == 0) partS[m * 2 + h] = ss;
            uint2 hi, lo; split4(v, hi, lo);
            uint32_t a1 = (uint32_t)m * ROWB + (uint32_t)f4 * 8u;
            *(uint2*)(smc + SMO_AHI + a1) = hi;
            *(uint2*)(smc + SMO_ALO + a1) = lo;
        }
    }
    // ---- Load + split K [64,256] ----
    {
        const int h  = wid & 1;
        const int wr = wid >> 1;
        const int f4 = h * 32 + lane;
        const float4* kg = (const float4*)pm_K + (size_t)pair * (R_ * D_ / 4);
        #pragma unroll 4
        for (int k = 0; k < 16; ++k) {
            int r = 4 * k + wr;
            float4 v = kg[(size_t)r * 64 + f4];
            uint2 hi, lo; split4(v, hi, lo);
            uint32_t a1 = (uint32_t)r * ROWB + (uint32_t)f4 * 8u;
            *(uint2*)(smc + SMO_BHI + a1) = hi;
            *(uint2*)(smc + SMO_BLO + a1) = lo;
        }
    }
    if (tid < R_) saS[tid] = pm_a[(size_t)pair * R_ + tid];
    __syncthreads();

    if (tid < MTILE)
        invS[tid] = 1.0f / fmaxf(sqrtf(partS[2 * tid] + partS[2 * tid + 1]), 1e-8f);
    __syncthreads();

    // ============ GEMM1 (split-K): warp tile 32x64, group kg owns K-half ============
    const int rg = wid & 3;          // row group: rows 32*rg .. +32
    const int kg = wid >> 2;         // K-half group

    float acc[2][8][4];
    #pragma unroll
    for (int mt = 0; mt < 2; ++mt)
        #pragma unroll
        for (int nt = 0; nt < 8; ++nt)
            #pragma unroll
            for (int i = 0; i < 4; ++i) acc[mt][nt][i] = 0.f;

    const uint32_t aOff = (uint32_t)(32 * rg + (lane & 15)) * ROWB +
                          (uint32_t)(lane >> 4) * 16u + (uint32_t)kg * 256u;
    const uint32_t bOff = (uint32_t)((lane & 7) + ((lane & 16) >> 1)) * ROWB +
                          (uint32_t)((lane >> 3) & 1) * 16u + (uint32_t)kg * 256u;

    #pragma unroll 1
    for (int p = 0; p < 3; ++p) {
        const uint32_t aBase = smb + (p == 2 ? SMO_ALO : SMO_AHI) + aOff;
        const uint32_t bBase = smb + (p == 1 ? SMO_BLO : SMO_BHI) + bOff;
        #pragma unroll
        for (int k = 0; k < 8; ++k) {
            uint32_t a0[4], a1[4];
            ldsm4(a0, aBase + (uint32_t)k * 32u);
            ldsm4(a1, aBase + 16u * ROWB + (uint32_t)k * 32u);
            #pragma unroll
            for (int g = 0; g < 4; ++g) {
                uint32_t bb[4];
                ldsm4(bb, bBase + (uint32_t)g * (16u * ROWB) + (uint32_t)k * 32u);
                mma16816(acc[0][2 * g + 0], a0, bb + 0);
                mma16816(acc[0][2 * g + 1], a0, bb + 2);
                mma16816(acc[1][2 * g + 0], a1, bb + 0);
                mma16816(acc[1][2 * g + 1], a1, bb + 2);
            }
        }
    }
    __syncthreads();   // K buffers now dead; RED overlays them

    // ---- STS partial acc into RED(kg) ----
    {
        const uint32_t red = smb + SMO_BHI + (uint32_t)kg * REDSZ;
        #pragma unroll
        for (int mt = 0; mt < 2; ++mt)
            #pragma unroll
            for (int nt = 0; nt < 8; ++nt)
                #pragma unroll
                for (int h = 0; h < 2; ++h) {
                    uint32_t addr = red +
                        (uint32_t)(32 * rg + 16 * mt + (lane >> 2) + 8 * h) * 264u +
                        (uint32_t)(8 * nt + 2 * (lane & 3)) * 4u;
                    asm volatile("st.shared.v2.f32 [%0], {%1,%2};"
                                 :: "r"(addr), "f"(acc[mt][nt][2 * h]),
                                    "f"(acc[mt][nt][2 * h + 1]) : "memory");
                }
    }
    __syncthreads();
    // ---- LDS other group's partial + add ----
    {
        const uint32_t red = smb + SMO_BHI + (uint32_t)(1 - kg) * REDSZ;
        #pragma unroll
        for (int mt = 0; mt < 2; ++mt)
            #pragma unroll
            for (int nt = 0; nt < 8; ++nt)
                #pragma unroll
                for (int h = 0; h < 2; ++h) {
                    uint32_t addr = red +
                        (uint32_t)(32 * rg + 16 * mt + (lane >> 2) + 8 * h) * 264u +
                        (uint32_t)(8 * nt + 2 * (lane & 3)) * 4u;
                    float x, y;
                    asm volatile("ld.shared.v2.f32 {%0,%1}, [%2];"
                                 : "=f"(x), "=f"(y) : "r"(addr));
                    acc[mt][nt][2 * h]     += x;
                    acc[mt][nt][2 * h + 1] += y;
                }
    }

    // ---- Epilogue1: w = score * inv -> bf16 hi/lo A-fragments (registers) ----
    uint32_t whi[2][4][4], wlo[2][4][4];
    #pragma unroll
    for (int mt = 0; mt < 2; ++mt) {
        const int r0 = 32 * rg + 16 * mt + (lane >> 2);
        const float inv0 = invS[r0], inv1 = invS[r0 + 8];
        #pragma unroll
        for (int kt = 0; kt < 4; ++kt) {
            #pragma unroll
            for (int hf = 0; hf < 2; ++hf) {
                const int nt = 2 * kt + hf;
                float w00 = acc[mt][nt][0] * inv0, w01 = acc[mt][nt][1] * inv0;
                float w10 = acc[mt][nt][2] * inv1, w11 = acc[mt][nt][3] * inv1;
                __nv_bfloat16 h00 = __float2bfloat16_rn(w00), h01 = __float2bfloat16_rn(w01);
                __nv_bfloat16 h10 = __float2bfloat16_rn(w10), h11 = __float2bfloat16_rn(w11);
                whi[mt][kt][2 * hf + 0] = (uint32_t)__bfloat16_as_ushort(h00) |
                                          ((uint32_t)__bfloat16_as_ushort(h01) << 16);
                whi[mt][kt][2 * hf + 1] = (uint32_t)__bfloat16_as_ushort(h10) |
                                          ((uint32_t)__bfloat16_as_ushort(h11) << 16);
                wlo[mt][kt][2 * hf + 0] = packbf(w00 - __bfloat162float(h00),
                                                 w01 - __bfloat162float(h01));
                wlo[mt][kt][2 * hf + 1] = packbf(w10 - __bfloat162float(h10),
                                                 w11 - __bfloat162float(h11));
            }
        }
    }
    __syncthreads();   // RED reads done; B region free for V

    // ---- Load + split V (pm_a folded in) into B buffers ----
    {
        const int h  = wid & 1;
        const int wr = wid >> 1;
        const int f4 = h * 32 + lane;
        const float4* vg = (const float4*)pm_V + (size_t)pair * (R_ * D_ / 4);
        #pragma unroll 4
        for (int k = 0; k < 16; ++k) {
            int r = 4 * k + wr;
            float av = saS[r];
            float4 v = vg[(size_t)r * 64 + f4];
            v.x *= av; v.y *= av; v.z *= av; v.w *= av;
            uint2 hi, lo; split4(v, hi, lo);
            uint32_t a1 = (uint32_t)r * ROWB + (uint32_t)f4 * 8u;
            *(uint2*)(smc + SMO_BHI + a1) = hi;
            *(uint2*)(smc + SMO_BLO + a1) = lo;
        }
    }
    __syncthreads();

    // ============ GEMM2: mod[128,256] = W . V'; warp: 32 rows x 2 chunks of 64 ============
    const uint32_t vOff = (uint32_t)(lane & 15) * ROWB + (uint32_t)(lane >> 4) * 16u;

    #pragma unroll 1
    for (int i = 0; i < 2; ++i) {
        const int j = 2 * kg + i;
        #pragma unroll
        for (int mt = 0; mt < 2; ++mt)
            #pragma unroll
            for (int nt = 0; nt < 8; ++nt)
                #pragma unroll
                for (int z = 0; z < 4; ++z) acc[mt][nt][z] = 0.f;

        #pragma unroll 1
        for (int p = 0; p < 3; ++p) {
            const uint32_t (*A)[4][4] = (p == 2) ? wlo : whi;
            const uint32_t bBase = smb + (p == 1 ? SMO_BLO : SMO_BHI) + vOff +
                                   (uint32_t)j * 128u;
            #pragma unroll
            for (int k = 0; k < 4; ++k) {
                #pragma unroll
                for (int g = 0; g < 4; ++g) {
                    uint32_t bb[4];
                    ldsm4t(bb, bBase + (uint32_t)k * (16u * ROWB) + (uint32_t)g * 32u);
                    mma16816(acc[0][2 * g + 0], A[0][k], bb + 0);
                    mma16816(acc[0][2 * g + 1], A[0][k], bb + 2);
                    mma16816(acc[1][2 * g + 0], A[1][k], bb + 0);
                    mma16816(acc[1][2 * g + 1], A[1][k], bb + 2);
                }
            }
        }

        // ---- Epilogue2: out = q * mod (q re-read from gmem, L2-resident) ----
        #pragma unroll
        for (int mt = 0; mt < 2; ++mt) {
            #pragma unroll
            for (int h = 0; h < 2; ++h) {
                const int m = 32 * rg + 16 * mt + (lane >> 2) + 8 * h;
                const size_t gbase = ((size_t)(s * N_ + n0 + m) * B_ + b) * D_;
                #pragma unroll
                for (int nt = 0; nt < 8; ++nt) {
                    const int col = 64 * j + 8 * nt + 2 * (lane & 3);
                    float2 qv = *(const float2*)(q + gbase + col);
                    float2 o;
                    o.x = qv.x * acc[mt][nt][2 * h];
                    o.y = qv.y * acc[mt][nt][2 * h + 1];
                    *(float2*)(out + gbase + col) = o;
                }
            }
        }
    }
}

extern "C" void kernel_launch(void* const* d_in, const int* in_sizes, int n_in,
                              void* d_out, int out_size)
{
    const float* q    = (const float*)d_in[0];
    const float* pm_K = (const float*)d_in[1];
    const float* pm_V = (const float*)d_in[2];
    const float* pm_a = (const float*)d_in[3];
    float* out = (float*)d_out;

    cudaFuncSetAttribute(ProceduralMemory_81535659147884_kernel,
                         cudaFuncAttributeMaxDynamicSharedMemorySize, SMEM_TOTAL);

    dim3 grid(BS_ * B_ * (N_ / MTILE));   // 2048 CTAs
    ProceduralMemory_81535659147884_kernel<<<grid, THREADS, SMEM_TOTAL>>>(
        q, pm_K, pm_V, pm_a, out);
}

// round 5
// speedup vs baseline: 1.0127x; 1.0127x over previous
#include <cuda_runtime.h>
#include <cuda_bf16.h>
#include <cstdint>

#define BS_  8
#define N_   4096
#define B_   8
#define R_   64
#define D_   256

#define MTILE   64
#define THREADS 128
#define ROWB    272        // bytes per smem row: 136 bf16 (128 data + 8 pad)

// ---- smem layout (bytes) ----
#define SMO_AHI  0                      // q chunk hi  [64][136] bf16 = 17408
#define SMO_ALO  17408                  // q chunk lo
#define SMO_BHI  34816                  // K/V chunk hi [64][136]
#define SMO_BLO  52224                  // K/V chunk lo
#define SMO_PART 69632                  // 128 floats: ssq partials [64][2]
#define SMO_INV  70144                  // 64 floats
#define SMO_SA   70400                  // 64 floats pm_a
#define SMEM_TOTAL 70656

__device__ __forceinline__ uint32_t smem_u32(const void* p) {
    uint32_t a;
    asm("{ .reg .u64 t; cvta.to.shared.u64 t, %1; cvt.u32.u64 %0, t; }" : "=r"(a) : "l"(p));
    return a;
}
__device__ __forceinline__ void ldsm4(uint32_t* r, uint32_t addr) {
    asm volatile("ldmatrix.sync.aligned.m8n8.x4.shared.b16 {%0,%1,%2,%3}, [%4];"
                 : "=r"(r[0]), "=r"(r[1]), "=r"(r[2]), "=r"(r[3]) : "r"(addr));
}
__device__ __forceinline__ void ldsm4t(uint32_t* r, uint32_t addr) {
    asm volatile("ldmatrix.sync.aligned.m8n8.x4.trans.shared.b16 {%0,%1,%2,%3}, [%4];"
                 : "=r"(r[0]), "=r"(r[1]), "=r"(r[2]), "=r"(r[3]) : "r"(addr));
}
__device__ __forceinline__ void mma16816(float* c, const uint32_t* a, const uint32_t* b) {
    asm volatile("mma.sync.aligned.m16n8k16.row.col.f32.bf16.bf16.f32 "
                 "{%0,%1,%2,%3}, {%4,%5,%6,%7}, {%8,%9}, {%0,%1,%2,%3};"
                 : "+f"(c[0]), "+f"(c[1]), "+f"(c[2]), "+f"(c[3])
                 : "r"(a[0]), "r"(a[1]), "r"(a[2]), "r"(a[3]), "r"(b[0]), "r"(b[1]));
}
__device__ __forceinline__ uint32_t packbf(float x, float y) {
    __nv_bfloat162 h = __floats2bfloat162_rn(x, y);
    return *(uint32_t*)&h;
}
__device__ __forceinline__ void split4(float4 v, uint2& hi, uint2& lo) {
    __nv_bfloat16 hx = __float2bfloat16_rn(v.x), hy = __float2bfloat16_rn(v.y);
    __nv_bfloat16 hz = __float2bfloat16_rn(v.z), hw = __float2bfloat16_rn(v.w);
    hi.x = (uint32_t)__bfloat16_as_ushort(hx) | ((uint32_t)__bfloat16_as_ushort(hy) << 16);
    hi.y = (uint32_t)__bfloat16_as_ushort(hz) | ((uint32_t)__bfloat16_as_ushort(hw) << 16);
    lo.x = packbf(v.x - __bfloat162float(hx), v.y - __bfloat162float(hy));
    lo.y = packbf(v.z - __bfloat162float(hz), v.w - __bfloat162float(hw));
}

__global__ __launch_bounds__(THREADS, 2)
void ProceduralMemory_81535659147884_kernel(
    const float* __restrict__ q,
    const float* __restrict__ pm_K,
    const float* __restrict__ pm_V,
    const float* __restrict__ pm_a,
    float* __restrict__ out)
{
    extern __shared__ char smc[];
    const uint32_t smb = smem_u32(smc);

    const int tid  = threadIdx.x;
    const int wid  = tid >> 5;        // 0..3
    const int lane = tid & 31;

    const int pair = blockIdx.x >> 6;          // 0..63
    const int tile = blockIdx.x & 63;          // 0..63
    const int s = pair >> 3, b = pair & 7;
    const int n0 = tile * MTILE;

    float* partS = (float*)(smc + SMO_PART);
    float* invS  = (float*)(smc + SMO_INV);
    float* saS   = (float*)(smc + SMO_SA);

    if (tid < R_) saS[tid] = pm_a[(size_t)pair * R_ + tid];

    // GEMM1 accumulators: warp tile 16 rows x 64 n, persist over 2 K-chunks
    float acc[8][4];
    #pragma unroll
    for (int nt = 0; nt < 8; ++nt)
        #pragma unroll
        for (int i = 0; i < 4; ++i) acc[nt][i] = 0.f;

    const uint32_t aOff = (uint32_t)(16 * wid + (lane & 15)) * ROWB +
                          (uint32_t)(lane >> 4) * 16u;
    const uint32_t bOff = (uint32_t)((lane & 7) + ((lane & 16) >> 1)) * ROWB +
                          (uint32_t)((lane >> 3) & 1) * 16u;

    #pragma unroll 1
    for (int c = 0; c < 2; ++c) {
        if (c > 0) __syncthreads();   // GEMM1 chunk0 done reading buffers

        // ---- Load + split q chunk [64 rows, cols 128c..] ----
        {
            const float4* qg = (const float4*)q;
            #pragma unroll 4
            for (int rr = 0; rr < 16; ++rr) {
                const int m = 16 * wid + rr;
                float4 v = qg[((size_t)(s * N_ + n0 + m) * B_ + b) * 64 + c * 32 + lane];
                float ss = v.x * v.x + v.y * v.y + v.z * v.z + v.w * v.w;
                #pragma unroll
                for (int o = 16; o; o >>= 1) ss += __shfl_xor_sync(0xFFFFFFFFu, ss, o);
                if (lane == 0) partS[m * 2 + c] = ss;
                uint2 hi, lo; split4(v, hi, lo);
                uint32_t a1 = (uint32_t)m * ROWB + (uint32_t)lane * 8u;
                *(uint2*)(smc + SMO_AHI + a1) = hi;
                *(uint2*)(smc + SMO_ALO + a1) = lo;
            }
        }
        // ---- Load + split K chunk [64 r, cols 128c..] ----
        {
            const float4* kg = (const float4*)pm_K + (size_t)pair * (R_ * D_ / 4);
            #pragma unroll 4
            for (int rr = 0; rr < 16; ++rr) {
                const int r = 16 * wid + rr;
                float4 v = kg[(size_t)r * 64 + c * 32 + lane];
                uint2 hi, lo; split4(v, hi, lo);
                uint32_t a1 = (uint32_t)r * ROWB + (uint32_t)lane * 8u;
                *(uint2*)(smc + SMO_BHI + a1) = hi;
                *(uint2*)(smc + SMO_BLO + a1) = lo;
            }
        }
        __syncthreads();

        if (c == 1 && tid < MTILE)
            invS[tid] = 1.0f / fmaxf(sqrtf(partS[2 * tid] + partS[2 * tid + 1]), 1e-8f);

        // ---- GEMM1 partial: 3 bf16-split passes over this 128-col chunk ----
        #pragma unroll 1
        for (int p = 0; p < 3; ++p) {
            const uint32_t aBase = smb + (p == 2 ? SMO_ALO : SMO_AHI) + aOff;
            const uint32_t bBase = smb + (p == 1 ? SMO_BLO : SMO_BHI) + bOff;
            #pragma unroll
            for (int k = 0; k < 8; ++k) {
                uint32_t a[4];
                ldsm4(a, aBase + (uint32_t)k * 32u);
                #pragma unroll
                for (int g = 0; g < 4; ++g) {
                    uint32_t bb[4];
                    ldsm4(bb, bBase + (uint32_t)g * (16u * ROWB) + (uint32_t)k * 32u);
                    mma16816(acc[2 * g + 0], a, bb + 0);
                    mma16816(acc[2 * g + 1], a, bb + 2);
                }
            }
        }
    }
    __syncthreads();   // GEMM1 done; B buffers free for V, invS visible

    // ---- Epilogue1: w = score * inv -> bf16 hi/lo A-fragments (registers) ----
    uint32_t whi[4][4], wlo[4][4];
    {
        const int r0 = 16 * wid + (lane >> 2);
        const float inv0 = invS[r0], inv1 = invS[r0 + 8];
        #pragma unroll
        for (int kt = 0; kt < 4; ++kt) {
            #pragma unroll
            for (int hf = 0; hf < 2; ++hf) {
                const int nt = 2 * kt + hf;
                float w00 = acc[nt][0] * inv0, w01 = acc[nt][1] * inv0;
                float w10 = acc[nt][2] * inv1, w11 = acc[nt][3] * inv1;
                __nv_bfloat16 h00 = __float2bfloat16_rn(w00), h01 = __float2bfloat16_rn(w01);
                __nv_bfloat16 h10 = __float2bfloat16_rn(w10), h11 = __float2bfloat16_rn(w11);
                whi[kt][2 * hf + 0] = (uint32_t)__bfloat16_as_ushort(h00) |
                                      ((uint32_t)__bfloat16_as_ushort(h01) << 16);
                whi[kt][2 * hf + 1] = (uint32_t)__bfloat16_as_ushort(h10) |
                                      ((uint32_t)__bfloat16_as_ushort(h11) << 16);
                wlo[kt][2 * hf + 0] = packbf(w00 - __bfloat162float(h00),
                                             w01 - __bfloat162float(h01));
                wlo[kt][2 * hf + 1] = packbf(w10 - __bfloat162float(h10),
                                             w11 - __bfloat162float(h11));
            }
        }
    }

    // ============ GEMM2: mod[64,256] = W . (a*V), two 128-col V chunks ============
    const uint32_t vOff = (uint32_t)(lane & 15) * ROWB + (uint32_t)(lane >> 4) * 16u;

    #pragma unroll 1
    for (int j = 0; j < 2; ++j) {
        if (j > 0) __syncthreads();   // previous GEMM2 chunk done reading V buffers

        // ---- Load + split V chunk (pm_a folded) ----
        {
            const float4* vg = (const float4*)pm_V + (size_t)pair * (R_ * D_ / 4);
            #pragma unroll 4
            for (int rr = 0; rr < 16; ++rr) {
                const int r = 16 * wid + rr;
                const float av = saS[r];
                float4 v = vg[(size_t)r * 64 + j * 32 + lane];
                v.x *= av; v.y *= av; v.z *= av; v.w *= av;
                uint2 hi, lo; split4(v, hi, lo);
                uint32_t a1 = (uint32_t)r * ROWB + (uint32_t)lane * 8u;
                *(uint2*)(smc + SMO_BHI + a1) = hi;
                *(uint2*)(smc + SMO_BLO + a1) = lo;
            }
        }
        __syncthreads();

        float acc2[16][4];
        #pragma unroll
        for (int nt = 0; nt < 16; ++nt)
            #pragma unroll
            for (int i = 0; i < 4; ++i) acc2[nt][i] = 0.f;

        #pragma unroll 1
        for (int p = 0; p < 3; ++p) {
            const uint32_t (*A)[4] = (p == 2) ? wlo : whi;
            const uint32_t bBase = smb + (p == 1 ? SMO_BLO : SMO_BHI) + vOff;
            #pragma unroll
            for (int k = 0; k < 4; ++k) {
                #pragma unroll
                for (int g = 0; g < 8; ++g) {
                    uint32_t bb[4];
                    ldsm4t(bb, bBase + (uint32_t)k * (16u * ROWB) + (uint32_t)g * 32u);
                    mma16816(acc2[2 * g + 0], A[k], bb + 0);
                    mma16816(acc2[2 * g + 1], A[k], bb + 2);
                }
            }
        }

        // ---- Epilogue2: out = q * mod (q re-read from gmem, L2-resident) ----
        #pragma unroll
        for (int h = 0; h < 2; ++h) {
            const int m = 16 * wid + (lane >> 2) + 8 * h;
            const size_t gbase = ((size_t)(s * N_ + n0 + m) * B_ + b) * D_;
            #pragma unroll
            for (int nt = 0; nt < 16; ++nt) {
                const int col = 128 * j + 8 * nt + 2 * (lane & 3);
                float2 qv = *(const float2*)(q + gbase + col);
                float2 o;
                o.x = qv.x * acc2[nt][2 * h];
                o.y = qv.y * acc2[nt][2 * h + 1];
                *(float2*)(out + gbase + col) = o;
            }
        }
    }
}

extern "C" void kernel_launch(void* const* d_in, const int* in_sizes, int n_in,
                              void* d_out, int out_size)
{
    const float* q    = (const float*)d_in[0];
    const float* pm_K = (const float*)d_in[1];
    const float* pm_V = (const float*)d_in[2];
    const float* pm_a = (const float*)d_in[3];
    float* out = (float*)d_out;

    cudaFuncSetAttribute(ProceduralMemory_81535659147884_kernel,
                         cudaFuncAttributeMaxDynamicSharedMemorySize, SMEM_TOTAL);

    dim3 grid(BS_ * B_ * (N_ / MTILE));   // 4096 CTAs
    ProceduralMemory_81535659147884_kernel<<<grid, THREADS, SMEM_TOTAL>>>(
        q, pm_K, pm_V, pm_a, out);
}

// round 6
// speedup vs baseline: 1.5210x; 1.5020x over previous
#include <cuda_runtime.h>
#include <cuda_fp16.h>
#include <cstdint>

#define BS_  8
#define N_   4096
#define B_   8
#define R_   64
#define D_   256

#define MTILE   64
#define THREADS 128
#define ROWB    272        // bytes per smem row: 136 fp16 (128 data + 8 pad)

// ---- smem layout (bytes) ----
#define SMO_AHI  0                      // q chunk hi  [64][136] fp16 = 17408
#define SMO_ALO  17408                  // q chunk lo
#define SMO_BB   34816                  // K/V chunk fp16 [64][136]
#define SMO_PART 52224                  // 128 floats: ssq partials [64][2]
#define SMO_INV  52736                  // 64 floats
#define SMO_SA   52992                  // 64 floats pm_a
#define SMEM_TOTAL 53248

__device__ __forceinline__ uint32_t smem_u32(const void* p) {
    uint32_t a;
    asm("{ .reg .u64 t; cvta.to.shared.u64 t, %1; cvt.u32.u64 %0, t; }" : "=r"(a) : "l"(p));
    return a;
}
__device__ __forceinline__ void ldsm4(uint32_t* r, uint32_t addr) {
    asm volatile("ldmatrix.sync.aligned.m8n8.x4.shared.b16 {%0,%1,%2,%3}, [%4];"
                 : "=r"(r[0]), "=r"(r[1]), "=r"(r[2]), "=r"(r[3]) : "r"(addr));
}
__device__ __forceinline__ void ldsm4t(uint32_t* r, uint32_t addr) {
    asm volatile("ldmatrix.sync.aligned.m8n8.x4.trans.shared.b16 {%0,%1,%2,%3}, [%4];"
                 : "=r"(r[0]), "=r"(r[1]), "=r"(r[2]), "=r"(r[3]) : "r"(addr));
}
__device__ __forceinline__ void mma16816(float* c, const uint32_t* a, const uint32_t* b) {
    asm volatile("mma.sync.aligned.m16n8k16.row.col.f32.f16.f16.f32 "
                 "{%0,%1,%2,%3}, {%4,%5,%6,%7}, {%8,%9}, {%0,%1,%2,%3};"
                 : "+f"(c[0]), "+f"(c[1]), "+f"(c[2]), "+f"(c[3])
                 : "r"(a[0]), "r"(a[1]), "r"(a[2]), "r"(a[3]), "r"(b[0]), "r"(b[1]));
}
__device__ __forceinline__ uint32_t packh2(float x, float y) {
    __half2 h = __floats2half2_rn(x, y);
    return *(uint32_t*)&h;
}
// split float4 into fp16 hi + fp16 residual lo
__device__ __forceinline__ void split4h(float4 v, uint2& hi, uint2& lo) {
    __half hx = __float2half_rn(v.x), hy = __float2half_rn(v.y);
    __half hz = __float2half_rn(v.z), hw = __float2half_rn(v.w);
    hi.x = (uint32_t)__half_as_ushort(hx) | ((uint32_t)__half_as_ushort(hy) << 16);
    hi.y = (uint32_t)__half_as_ushort(hz) | ((uint32_t)__half_as_ushort(hw) << 16);
    lo.x = packh2(v.x - __half2float(hx), v.y - __half2float(hy));
    lo.y = packh2(v.z - __half2float(hz), v.w - __half2float(hw));
}
__device__ __forceinline__ void cvt4h(float4 v, uint2& hi) {
    __half hx = __float2half_rn(v.x), hy = __float2half_rn(v.y);
    __half hz = __float2half_rn(v.z), hw = __float2half_rn(v.w);
    hi.x = (uint32_t)__half_as_ushort(hx) | ((uint32_t)__half_as_ushort(hy) << 16);
    hi.y = (uint32_t)__half_as_ushort(hz) | ((uint32_t)__half_as_ushort(hw) << 16);
}

__global__ __launch_bounds__(THREADS, 3)
void ProceduralMemory_81535659147884_kernel(
    const float* __restrict__ q,
    const float* __restrict__ pm_K,
    const float* __restrict__ pm_V,
    const float* __restrict__ pm_a,
    float* __restrict__ out)
{
    extern __shared__ char smc[];
    const uint32_t smb = smem_u32(smc);

    const int tid  = threadIdx.x;
    const int wid  = tid >> 5;        // 0..3
    const int lane = tid & 31;

    const int pair = blockIdx.x >> 6;          // 0..63
    const int tile = blockIdx.x & 63;          // 0..63
    const int s = pair >> 3, b = pair & 7;
    const int n0 = tile * MTILE;

    float* partS = (float*)(smc + SMO_PART);
    float* invS  = (float*)(smc + SMO_INV);
    float* saS   = (float*)(smc + SMO_SA);

    if (tid < R_) saS[tid] = pm_a[(size_t)pair * R_ + tid];

    // GEMM1 accumulators: warp tile 16 rows x 64 n, persist over 2 K-chunks
    float acc[8][4];
    #pragma unroll
    for (int nt = 0; nt < 8; ++nt)
        #pragma unroll
        for (int i = 0; i < 4; ++i) acc[nt][i] = 0.f;

    const uint32_t aOff = (uint32_t)(16 * wid + (lane & 15)) * ROWB +
                          (uint32_t)(lane >> 4) * 16u;
    const uint32_t bOff = (uint32_t)((lane & 7) + ((lane & 16) >> 1)) * ROWB +
                          (uint32_t)((lane >> 3) & 1) * 16u;

    #pragma unroll 1
    for (int c = 0; c < 2; ++c) {
        if (c > 0) __syncthreads();   // GEMM1 chunk0 done reading buffers

        // ---- Load + split q chunk [64 rows, cols 128c..] ----
        {
            const float4* qg = (const float4*)q;
            #pragma unroll 4
            for (int rr = 0; rr < 16; ++rr) {
                const int m = 16 * wid + rr;
                float4 v = qg[((size_t)(s * N_ + n0 + m) * B_ + b) * 64 + c * 32 + lane];
                float ss = v.x * v.x + v.y * v.y + v.z * v.z + v.w * v.w;
                #pragma unroll
                for (int o = 16; o; o >>= 1) ss += __shfl_xor_sync(0xFFFFFFFFu, ss, o);
                if (lane == 0) partS[m * 2 + c] = ss;
                uint2 hi, lo; split4h(v, hi, lo);
                uint32_t a1 = (uint32_t)m * ROWB + (uint32_t)lane * 8u;
                *(uint2*)(smc + SMO_AHI + a1) = hi;
                *(uint2*)(smc + SMO_ALO + a1) = lo;
            }
        }
        // ---- Load K chunk (single fp16) ----
        {
            const float4* kg = (const float4*)pm_K + (size_t)pair * (R_ * D_ / 4);
            #pragma unroll 4
            for (int rr = 0; rr < 16; ++rr) {
                const int r = 16 * wid + rr;
                float4 v = kg[(size_t)r * 64 + c * 32 + lane];
                uint2 hi; cvt4h(v, hi);
                *(uint2*)(smc + SMO_BB + (uint32_t)r * ROWB + (uint32_t)lane * 8u) = hi;
            }
        }
        __syncthreads();

        if (c == 1 && tid < MTILE)
            invS[tid] = 1.0f / fmaxf(sqrtf(partS[2 * tid] + partS[2 * tid + 1]), 1e-8f);

        // ---- GEMM1 partial: shared-B, 2 A-passes (hi, lo) per k-step ----
        #pragma unroll
        for (int k = 0; k < 8; ++k) {
            uint32_t ah[4], al[4];
            ldsm4(ah, smb + SMO_AHI + aOff + (uint32_t)k * 32u);
            ldsm4(al, smb + SMO_ALO + aOff + (uint32_t)k * 32u);
            #pragma unroll
            for (int g = 0; g < 4; ++g) {
                uint32_t bb[4];
                ldsm4(bb, smb + SMO_BB + bOff + (uint32_t)g * (16u * ROWB) +
                          (uint32_t)k * 32u);
                mma16816(acc[2 * g + 0], ah, bb + 0);
                mma16816(acc[2 * g + 1], ah, bb + 2);
                mma16816(acc[2 * g + 0], al, bb + 0);
                mma16816(acc[2 * g + 1], al, bb + 2);
            }
        }
    }
    __syncthreads();   // GEMM1 done; B buffer free for V, invS visible

    // ---- Epilogue1: w = score * inv -> fp16 hi/lo A-fragments (registers) ----
    uint32_t whi[4][4], wlo[4][4];
    {
        const int r0 = 16 * wid + (lane >> 2);
        const float inv0 = invS[r0], inv1 = invS[r0 + 8];
        #pragma unroll
        for (int kt = 0; kt < 4; ++kt) {
            #pragma unroll
            for (int hf = 0; hf < 2; ++hf) {
                const int nt = 2 * kt + hf;
                float w00 = acc[nt][0] * inv0, w01 = acc[nt][1] * inv0;
                float w10 = acc[nt][2] * inv1, w11 = acc[nt][3] * inv1;
                __half h00 = __float2half_rn(w00), h01 = __float2half_rn(w01);
                __half h10 = __float2half_rn(w10), h11 = __float2half_rn(w11);
                whi[kt][2 * hf + 0] = (uint32_t)__half_as_ushort(h00) |
                                      ((uint32_t)__half_as_ushort(h01) << 16);
                whi[kt][2 * hf + 1] = (uint32_t)__half_as_ushort(h10) |
                                      ((uint32_t)__half_as_ushort(h11) << 16);
                wlo[kt][2 * hf + 0] = packh2(w00 - __half2float(h00),
                                             w01 - __half2float(h01));
                wlo[kt][2 * hf + 1] = packh2(w10 - __half2float(h10),
                                             w11 - __half2float(h11));
            }
        }
    }

    // ============ GEMM2: mod[64,256] = W . (a*V), two 128-col V chunks ============
    const uint32_t vOff = (uint32_t)(lane & 15) * ROWB + (uint32_t)(lane >> 4) * 16u;

    #pragma unroll 1
    for (int j = 0; j < 2; ++j) {
        if (j > 0) __syncthreads();   // previous GEMM2 chunk done reading V buffer

        // ---- Load V chunk fp16 (pm_a folded) ----
        {
            const float4* vg = (const float4*)pm_V + (size_t)pair * (R_ * D_ / 4);
            #pragma unroll 4
            for (int rr = 0; rr < 16; ++rr) {
                const int r = 16 * wid + rr;
                const float av = saS[r];
                float4 v = vg[(size_t)r * 64 + j * 32 + lane];
                v.x *= av; v.y *= av; v.z *= av; v.w *= av;
                uint2 hi; cvt4h(v, hi);
                *(uint2*)(smc + SMO_BB + (uint32_t)r * ROWB + (uint32_t)lane * 8u) = hi;
            }
        }
        __syncthreads();

        #pragma unroll 1
        for (int sub = 0; sub < 2; ++sub) {     // 64 output cols at a time
            float acc2[8][4];
            #pragma unroll
            for (int nt = 0; nt < 8; ++nt)
                #pragma unroll
                for (int i = 0; i < 4; ++i) acc2[nt][i] = 0.f;

            #pragma unroll
            for (int k = 0; k < 4; ++k) {
                #pragma unroll
                for (int g = 0; g < 4; ++g) {
                    uint32_t bb[4];
                    ldsm4t(bb, smb + SMO_BB + vOff + (uint32_t)k * (16u * ROWB) +
                               (uint32_t)sub * 128u + (uint32_t)g * 32u);
                    mma16816(acc2[2 * g + 0], whi[k], bb + 0);
                    mma16816(acc2[2 * g + 1], whi[k], bb + 2);
                    mma16816(acc2[2 * g + 0], wlo[k], bb + 0);
                    mma16816(acc2[2 * g + 1], wlo[k], bb + 2);
                }
            }

            // ---- Epilogue2: out = q * mod (q re-read from gmem, L2-resident) ----
            #pragma unroll
            for (int h = 0; h < 2; ++h) {
                const int m = 16 * wid + (lane >> 2) + 8 * h;
                const size_t gbase = ((size_t)(s * N_ + n0 + m) * B_ + b) * D_;
                #pragma unroll
                for (int nt = 0; nt < 8; ++nt) {
                    const int col = 128 * j + 64 * sub + 8 * nt + 2 * (lane & 3);
                    float2 qv = *(const float2*)(q + gbase + col);
                    float2 o;
                    o.x = qv.x * acc2[nt][2 * h];
                    o.y = qv.y * acc2[nt][2 * h + 1];
                    *(float2*)(out + gbase + col) = o;
                }
            }
        }
    }
}

extern "C" void kernel_launch(void* const* d_in, const int* in_sizes, int n_in,
                              void* d_out, int out_size)
{
    const float* q    = (const float*)d_in[0];
    const float* pm_K = (const float*)d_in[1];
    const float* pm_V = (const float*)d_in[2];
    const float* pm_a = (const float*)d_in[3];
    float* out = (float*)d_out;

    cudaFuncSetAttribute(ProceduralMemory_81535659147884_kernel,
                         cudaFuncAttributeMaxDynamicSharedMemorySize, SMEM_TOTAL);

    dim3 grid(BS_ * B_ * (N_ / MTILE));   // 4096 CTAs
    ProceduralMemory_81535659147884_kernel<<<grid, THREADS, SMEM_TOTAL>>>(
        q, pm_K, pm_V, pm_a, out);
}

// round 7
// speedup vs baseline: 1.6817x; 1.1057x over previous
#include <cuda_runtime.h>
#include <cuda_fp16.h>
#include <cstdint>

#define BS_  8
#define N_   4096
#define B_   8
#define R_   64
#define D_   256

#define MTILE   64
#define THREADS 128
#define ROWB    272        // bytes per smem row: 136 fp16 (128 data + 8 pad)

// ---- smem layout (bytes) ----
#define SMO_AHI  0                      // q chunk hi  [64][136] fp16 = 17408
#define SMO_ALO  17408                  // q chunk lo
#define SMO_BB   34816                  // K/V chunk fp16 [64][136]
#define SMO_PART 52224                  // 128 floats: ssq partials [64][2]
#define SMO_INV  52736                  // 64 floats
#define SMO_SA   52992                  // 64 floats pm_a
#define SMEM_TOTAL 53248

__device__ __forceinline__ uint32_t smem_u32(const void* p) {
    uint32_t a;
    asm("{ .reg .u64 t; cvta.to.shared.u64 t, %1; cvt.u32.u64 %0, t; }" : "=r"(a) : "l"(p));
    return a;
}
__device__ __forceinline__ void ldsm4(uint32_t* r, uint32_t addr) {
    asm volatile("ldmatrix.sync.aligned.m8n8.x4.shared.b16 {%0,%1,%2,%3}, [%4];"
                 : "=r"(r[0]), "=r"(r[1]), "=r"(r[2]), "=r"(r[3]) : "r"(addr));
}
__device__ __forceinline__ void ldsm4t(uint32_t* r, uint32_t addr) {
    asm volatile("ldmatrix.sync.aligned.m8n8.x4.trans.shared.b16 {%0,%1,%2,%3}, [%4];"
                 : "=r"(r[0]), "=r"(r[1]), "=r"(r[2]), "=r"(r[3]) : "r"(addr));
}
__device__ __forceinline__ void mma16816(float* c, const uint32_t* a, const uint32_t* b) {
    asm volatile("mma.sync.aligned.m16n8k16.row.col.f32.f16.f16.f32 "
                 "{%0,%1,%2,%3}, {%4,%5,%6,%7}, {%8,%9}, {%0,%1,%2,%3};"
                 : "+f"(c[0]), "+f"(c[1]), "+f"(c[2]), "+f"(c[3])
                 : "r"(a[0]), "r"(a[1]), "r"(a[2]), "r"(a[3]), "r"(b[0]), "r"(b[1]));
}
__device__ __forceinline__ uint32_t packh2(float x, float y) {
    __half2 h = __floats2half2_rn(x, y);
    return *(uint32_t*)&h;
}
// split float4 into fp16 hi + fp16 residual lo
__device__ __forceinline__ void split4h(float4 v, uint2& hi, uint2& lo) {
    __half hx = __float2half_rn(v.x), hy = __float2half_rn(v.y);
    __half hz = __float2half_rn(v.z), hw = __float2half_rn(v.w);
    hi.x = (uint32_t)__half_as_ushort(hx) | ((uint32_t)__half_as_ushort(hy) << 16);
    hi.y = (uint32_t)__half_as_ushort(hz) | ((uint32_t)__half_as_ushort(hw) << 16);
    lo.x = packh2(v.x - __half2float(hx), v.y - __half2float(hy));
    lo.y = packh2(v.z - __half2float(hz), v.w - __half2float(hw));
}
__device__ __forceinline__ void cvt4h(float4 v, uint2& hi) {
    __half hx = __float2half_rn(v.x), hy = __float2half_rn(v.y);
    __half hz = __float2half_rn(v.z), hw = __float2half_rn(v.w);
    hi.x = (uint32_t)__half_as_ushort(hx) | ((uint32_t)__half_as_ushort(hy) << 16);
    hi.y = (uint32_t)__half_as_ushort(hz) | ((uint32_t)__half_as_ushort(hw) << 16);
}

__global__ __launch_bounds__(THREADS, 4)
void ProceduralMemory_81535659147884_kernel(
    const float* __restrict__ q,
    const float* __restrict__ pm_K,
    const float* __restrict__ pm_V,
    const float* __restrict__ pm_a,
    float* __restrict__ out)
{
    extern __shared__ char smc[];
    const uint32_t smb = smem_u32(smc);

    const int tid  = threadIdx.x;
    const int wid  = tid >> 5;        // 0..3
    const int lane = tid & 31;

    const int pair = blockIdx.x >> 6;          // 0..63
    const int tile = blockIdx.x & 63;          // 0..63
    const int s = pair >> 3, b = pair & 7;
    const int n0 = tile * MTILE;

    float* partS = (float*)(smc + SMO_PART);
    float* invS  = (float*)(smc + SMO_INV);
    float* saS   = (float*)(smc + SMO_SA);

    if (tid < R_) saS[tid] = pm_a[(size_t)pair * R_ + tid];

    // GEMM1 accumulators: warp tile 16 rows x 64 n, persist over 2 K-chunks
    float acc[8][4];
    #pragma unroll
    for (int nt = 0; nt < 8; ++nt)
        #pragma unroll
        for (int i = 0; i < 4; ++i) acc[nt][i] = 0.f;

    const uint32_t aOff = (uint32_t)(16 * wid + (lane & 15)) * ROWB +
                          (uint32_t)(lane >> 4) * 16u;
    const uint32_t bOff = (uint32_t)((lane & 7) + ((lane & 16) >> 1)) * ROWB +
                          (uint32_t)((lane >> 3) & 1) * 16u;

    #pragma unroll 1
    for (int c = 0; c < 2; ++c) {
        if (c > 0) __syncthreads();   // GEMM1 chunk0 done reading buffers

        // ---- Load + split q chunk [64 rows, cols 128c..] ----
        {
            const float4* qg = (const float4*)q;
            #pragma unroll 4
            for (int rr = 0; rr < 16; ++rr) {
                const int m = 16 * wid + rr;
                float4 v = qg[((size_t)(s * N_ + n0 + m) * B_ + b) * 64 + c * 32 + lane];
                float ss = v.x * v.x + v.y * v.y + v.z * v.z + v.w * v.w;
                #pragma unroll
                for (int o = 16; o; o >>= 1) ss += __shfl_xor_sync(0xFFFFFFFFu, ss, o);
                if (lane == 0) partS[m * 2 + c] = ss;
                uint2 hi, lo; split4h(v, hi, lo);
                uint32_t a1 = (uint32_t)m * ROWB + (uint32_t)lane * 8u;
                *(uint2*)(smc + SMO_AHI + a1) = hi;
                *(uint2*)(smc + SMO_ALO + a1) = lo;
            }
        }
        // ---- Load K chunk (single fp16) ----
        {
            const float4* kg = (const float4*)pm_K + (size_t)pair * (R_ * D_ / 4);
            #pragma unroll 4
            for (int rr = 0; rr < 16; ++rr) {
                const int r = 16 * wid + rr;
                float4 v = kg[(size_t)r * 64 + c * 32 + lane];
                uint2 hi; cvt4h(v, hi);
                *(uint2*)(smc + SMO_BB + (uint32_t)r * ROWB + (uint32_t)lane * 8u) = hi;
            }
        }
        __syncthreads();

        if (c == 1 && tid < MTILE)
            invS[tid] = 1.0f / fmaxf(sqrtf(partS[2 * tid] + partS[2 * tid + 1]), 1e-8f);

        // ---- GEMM1 partial: shared-B, 2 A-passes (hi, lo) per k-step ----
        #pragma unroll
        for (int k = 0; k < 8; ++k) {
            uint32_t ah[4], al[4];
            ldsm4(ah, smb + SMO_AHI + aOff + (uint32_t)k * 32u);
            ldsm4(al, smb + SMO_ALO + aOff + (uint32_t)k * 32u);
            #pragma unroll
            for (int g = 0; g < 4; ++g) {
                uint32_t bb[4];
                ldsm4(bb, smb + SMO_BB + bOff + (uint32_t)g * (16u * ROWB) +
                          (uint32_t)k * 32u);
                mma16816(acc[2 * g + 0], ah, bb + 0);
                mma16816(acc[2 * g + 1], ah, bb + 2);
                mma16816(acc[2 * g + 0], al, bb + 0);
                mma16816(acc[2 * g + 1], al, bb + 2);
            }
        }
    }
    __syncthreads();   // GEMM1 done; B buffer free for V, invS visible

    // ---- Epilogue1: w = score * inv -> fp16 hi/lo A-fragments (registers) ----
    uint32_t whi[4][4], wlo[4][4];
    {
        const int r0 = 16 * wid + (lane >> 2);
        const float inv0 = invS[r0], inv1 = invS[r0 + 8];
        #pragma unroll
        for (int kt = 0; kt < 4; ++kt) {
            #pragma unroll
            for (int hf = 0; hf < 2; ++hf) {
                const int nt = 2 * kt + hf;
                float w00 = acc[nt][0] * inv0, w01 = acc[nt][1] * inv0;
                float w10 = acc[nt][2] * inv1, w11 = acc[nt][3] * inv1;
                __half h00 = __float2half_rn(w00), h01 = __float2half_rn(w01);
                __half h10 = __float2half_rn(w10), h11 = __float2half_rn(w11);
                whi[kt][2 * hf + 0] = (uint32_t)__half_as_ushort(h00) |
                                      ((uint32_t)__half_as_ushort(h01) << 16);
                whi[kt][2 * hf + 1] = (uint32_t)__half_as_ushort(h10) |
                                      ((uint32_t)__half_as_ushort(h11) << 16);
                wlo[kt][2 * hf + 0] = packh2(w00 - __half2float(h00),
                                             w01 - __half2float(h01));
                wlo[kt][2 * hf + 1] = packh2(w10 - __half2float(h10),
                                             w11 - __half2float(h11));
            }
        }
    }

    // ============ GEMM2: mod[64,256] = W . (a*V), two 128-col V chunks ============
    const uint32_t vOff = (uint32_t)(lane & 15) * ROWB + (uint32_t)(lane >> 4) * 16u;

    #pragma unroll 1
    for (int j = 0; j < 2; ++j) {
        if (j > 0) __syncthreads();   // previous GEMM2 chunk done reading V buffer

        // ---- Load V chunk fp16 (pm_a folded) ----
        {
            const float4* vg = (const float4*)pm_V + (size_t)pair * (R_ * D_ / 4);
            #pragma unroll 4
            for (int rr = 0; rr < 16; ++rr) {
                const int r = 16 * wid + rr;
                const float av = saS[r];
                float4 v = vg[(size_t)r * 64 + j * 32 + lane];
                v.x *= av; v.y *= av; v.z *= av; v.w *= av;
                uint2 hi; cvt4h(v, hi);
                *(uint2*)(smc + SMO_BB + (uint32_t)r * ROWB + (uint32_t)lane * 8u) = hi;
            }
        }
        __syncthreads();

        #pragma unroll 1
        for (int sub = 0; sub < 2; ++sub) {     // 64 output cols at a time
            float acc2[8][4];
            #pragma unroll
            for (int nt = 0; nt < 8; ++nt)
                #pragma unroll
                for (int i = 0; i < 4; ++i) acc2[nt][i] = 0.f;

            #pragma unroll
            for (int k = 0; k < 4; ++k) {
                #pragma unroll
                for (int g = 0; g < 4; ++g) {
                    uint32_t bb[4];
                    ldsm4t(bb, smb + SMO_BB + vOff + (uint32_t)k * (16u * ROWB) +
                               (uint32_t)sub * 128u + (uint32_t)g * 32u);
                    mma16816(acc2[2 * g + 0], whi[k], bb + 0);
                    mma16816(acc2[2 * g + 1], whi[k], bb + 2);
                    mma16816(acc2[2 * g + 0], wlo[k], bb + 0);
                    mma16816(acc2[2 * g + 1], wlo[k], bb + 2);
                }
            }

            // ---- Epilogue2: out = q * mod (q re-read from gmem, L2-resident) ----
            #pragma unroll
            for (int h = 0; h < 2; ++h) {
                const int m = 16 * wid + (lane >> 2) + 8 * h;
                const size_t gbase = ((size_t)(s * N_ + n0 + m) * B_ + b) * D_;
                #pragma unroll
                for (int nt = 0; nt < 8; ++nt) {
                    const int col = 128 * j + 64 * sub + 8 * nt + 2 * (lane & 3);
                    float2 qv = *(const float2*)(q + gbase + col);
                    float2 o;
                    o.x = qv.x * acc2[nt][2 * h];
                    o.y = qv.y * acc2[nt][2 * h + 1];
                    *(float2*)(out + gbase + col) = o;
                }
            }
        }
    }
}

extern "C" void kernel_launch(void* const* d_in, const int* in_sizes, int n_in,
                              void* d_out, int out_size)
{
    const float* q    = (const float*)d_in[0];
    const float* pm_K = (const float*)d_in[1];
    const float* pm_V = (const float*)d_in[2];
    const float* pm_a = (const float*)d_in[3];
    float* out = (float*)d_out;

    cudaFuncSetAttribute(ProceduralMemory_81535659147884_kernel,
                         cudaFuncAttributeMaxDynamicSharedMemorySize, SMEM_TOTAL);

    dim3 grid(BS_ * B_ * (N_ / MTILE));   // 4096 CTAs
    ProceduralMemory_81535659147884_kernel<<<grid, THREADS, SMEM_TOTAL>>>(
        q, pm_K, pm_V, pm_a, out);
}

// round 8
// speedup vs baseline: 2.0323x; 1.2084x over previous
#include <cuda_runtime.h>
#include <cuda_fp16.h>
#include <cstdint>

#define BS_  8
#define N_   4096
#define B_   8
#define R_   64
#define D_   256

#define MTILE   64
#define THREADS 128
#define ROWB    272        // bytes per smem row: 136 fp16 (128 data + 8 pad)

#define KV_ELEMS (BS_*B_*R_*D_)   // 1,048,576

// ---- smem layout (bytes) ----
#define SMO_AHI  0                      // q chunk hi  [64][136] fp16 = 17408
#define SMO_ALO  17408                  // q chunk lo
#define SMO_BB   34816                  // K/V chunk fp16 [64][136]
#define SMO_PART 52224                  // 128 floats: ssq partials [64][2]
#define SMO_INV  52736                  // 64 floats
#define SMEM_TOTAL 53248

// Pre-converted K and a*V (fp16), written by the prelude kernel.
__device__ __half g_Kf[KV_ELEMS];
__device__ __half g_Vf[KV_ELEMS];

__global__ __launch_bounds__(256)
void ProceduralMemory_81535659147884_cvt(const float* __restrict__ K,
                                         const float* __restrict__ V,
                                         const float* __restrict__ a)
{
    const int idx = blockIdx.x * 256 + threadIdx.x;      // per float2
    const float2 k2 = ((const float2*)K)[idx];
    const float2 v2 = ((const float2*)V)[idx];
    const float av = a[idx / (D_ / 2)];
    ((__half2*)g_Kf)[idx] = __floats2half2_rn(k2.x, k2.y);
    ((__half2*)g_Vf)[idx] = __floats2half2_rn(v2.x * av, v2.y * av);
}

__device__ __forceinline__ uint32_t smem_u32(const void* p) {
    uint32_t a;
    asm("{ .reg .u64 t; cvta.to.shared.u64 t, %1; cvt.u32.u64 %0, t; }" : "=r"(a) : "l"(p));
    return a;
}
__device__ __forceinline__ void cpa16(uint32_t dst, const void* src) {
    asm volatile("cp.async.cg.shared.global [%0], [%1], 16;" :: "r"(dst), "l"(src));
}
__device__ __forceinline__ void ldsm4(uint32_t* r, uint32_t addr) {
    asm volatile("ldmatrix.sync.aligned.m8n8.x4.shared.b16 {%0,%1,%2,%3}, [%4];"
                 : "=r"(r[0]), "=r"(r[1]), "=r"(r[2]), "=r"(r[3]) : "r"(addr));
}
__device__ __forceinline__ void ldsm4t(uint32_t* r, uint32_t addr) {
    asm volatile("ldmatrix.sync.aligned.m8n8.x4.trans.shared.b16 {%0,%1,%2,%3}, [%4];"
                 : "=r"(r[0]), "=r"(r[1]), "=r"(r[2]), "=r"(r[3]) : "r"(addr));
}
__device__ __forceinline__ void mma16816(float* c, const uint32_t* a, const uint32_t* b) {
    asm volatile("mma.sync.aligned.m16n8k16.row.col.f32.f16.f16.f32 "
                 "{%0,%1,%2,%3}, {%4,%5,%6,%7}, {%8,%9}, {%0,%1,%2,%3};"
                 : "+f"(c[0]), "+f"(c[1]), "+f"(c[2]), "+f"(c[3])
                 : "r"(a[0]), "r"(a[1]), "r"(a[2]), "r"(a[3]), "r"(b[0]), "r"(b[1]));
}
__device__ __forceinline__ uint32_t packh2(float x, float y) {
    __half2 h = __floats2half2_rn(x, y);
    return *(uint32_t*)&h;
}
// split float4 into fp16 hi + fp16 residual lo
__device__ __forceinline__ void split4h(float4 v, uint2& hi, uint2& lo) {
    __half hx = __float2half_rn(v.x), hy = __float2half_rn(v.y);
    __half hz = __float2half_rn(v.z), hw = __float2half_rn(v.w);
    hi.x = (uint32_t)__half_as_ushort(hx) | ((uint32_t)__half_as_ushort(hy) << 16);
    hi.y = (uint32_t)__half_as_ushort(hz) | ((uint32_t)__half_as_ushort(hw) << 16);
    lo.x = packh2(v.x - __half2float(hx), v.y - __half2float(hy));
    lo.y = packh2(v.z - __half2float(hz), v.w - __half2float(hw));
}

__global__ __launch_bounds__(THREADS, 4)
void ProceduralMemory_81535659147884_kernel(
    const float* __restrict__ q,
    float* __restrict__ out)
{
    extern __shared__ char smc[];
    const uint32_t smb = smem_u32(smc);

    const int tid  = threadIdx.x;
    const int wid  = tid >> 5;        // 0..3
    const int lane = tid & 31;

    const int pair = blockIdx.x >> 6;          // 0..63
    const int tile = blockIdx.x & 63;          // 0..63
    const int s = pair >> 3, b = pair & 7;
    const int n0 = tile * MTILE;

    float* partS = (float*)(smc + SMO_PART);
    float* invS  = (float*)(smc + SMO_INV);

    // GEMM1 accumulators: warp tile 16 rows x 64 n, persist over 2 K-chunks
    float acc[8][4];
    #pragma unroll
    for (int nt = 0; nt < 8; ++nt)
        #pragma unroll
        for (int i = 0; i < 4; ++i) acc[nt][i] = 0.f;

    const uint32_t aOff = (uint32_t)(16 * wid + (lane & 15)) * ROWB +
                          (uint32_t)(lane >> 4) * 16u;
    const uint32_t bOff = (uint32_t)((lane & 7) + ((lane & 16) >> 1)) * ROWB +
                          (uint32_t)((lane >> 3) & 1) * 16u;

    #pragma unroll 1
    for (int c = 0; c < 2; ++c) {
        if (c > 0) __syncthreads();   // GEMM1 chunk0 done reading buffers

        // ---- Issue K chunk cp.async first (flies under the q work below) ----
        {
            const __half* ks = g_Kf + (size_t)pair * (R_ * D_) + c * 128;
            #pragma unroll
            for (int g = 0; g < 8; ++g) {
                const int idx = g * 128 + tid;        // 0..1023
                const int r = idx >> 4, gc = idx & 15;
                cpa16(smb + SMO_BB + (uint32_t)r * ROWB + (uint32_t)gc * 16u,
                      ks + (size_t)r * D_ + gc * 8);
            }
            asm volatile("cp.async.commit_group;" ::: "memory");
        }

        // ---- Load + split q chunk [64 rows, cols 128c..] ----
        {
            const float4* qg = (const float4*)q;
            #pragma unroll 4
            for (int rr = 0; rr < 16; ++rr) {
                const int m = 16 * wid + rr;
                float4 v = qg[((size_t)(s * N_ + n0 + m) * B_ + b) * 64 + c * 32 + lane];
                float ss = v.x * v.x + v.y * v.y + v.z * v.z + v.w * v.w;
                #pragma unroll
                for (int o = 16; o; o >>= 1) ss += __shfl_xor_sync(0xFFFFFFFFu, ss, o);
                if (lane == 0) partS[m * 2 + c] = ss;
                uint2 hi, lo; split4h(v, hi, lo);
                uint32_t a1 = (uint32_t)m * ROWB + (uint32_t)lane * 8u;
                *(uint2*)(smc + SMO_AHI + a1) = hi;
                *(uint2*)(smc + SMO_ALO + a1) = lo;
            }
        }
        asm volatile("cp.async.wait_group 0;" ::: "memory");
        __syncthreads();

        if (c == 1 && tid < MTILE)
            invS[tid] = 1.0f / fmaxf(sqrtf(partS[2 * tid] + partS[2 * tid + 1]), 1e-8f);

        // ---- GEMM1 partial: shared-B, 2 A-passes (hi, lo) per k-step ----
        #pragma unroll
        for (int k = 0; k < 8; ++k) {
            uint32_t ah[4], al[4];
            ldsm4(ah, smb + SMO_AHI + aOff + (uint32_t)k * 32u);
            ldsm4(al, smb + SMO_ALO + aOff + (uint32_t)k * 32u);
            #pragma unroll
            for (int g = 0; g < 4; ++g) {
                uint32_t bb[4];
                ldsm4(bb, smb + SMO_BB + bOff + (uint32_t)g * (16u * ROWB) +
                          (uint32_t)k * 32u);
                mma16816(acc[2 * g + 0], ah, bb + 0);
                mma16816(acc[2 * g + 1], ah, bb + 2);
                mma16816(acc[2 * g + 0], al, bb + 0);
                mma16816(acc[2 * g + 1], al, bb + 2);
            }
        }
    }
    __syncthreads();   // GEMM1 done; B buffer free for V, invS visible

    // ---- Epilogue1: w = score * inv -> fp16 hi/lo A-fragments (registers) ----
    uint32_t whi[4][4], wlo[4][4];
    {
        const int r0 = 16 * wid + (lane >> 2);
        const float inv0 = invS[r0], inv1 = invS[r0 + 8];
        #pragma unroll
        for (int kt = 0; kt < 4; ++kt) {
            #pragma unroll
            for (int hf = 0; hf < 2; ++hf) {
                const int nt = 2 * kt + hf;
                float w00 = acc[nt][0] * inv0, w01 = acc[nt][1] * inv0;
                float w10 = acc[nt][2] * inv1, w11 = acc[nt][3] * inv1;
                __half h00 = __float2half_rn(w00), h01 = __float2half_rn(w01);
                __half h10 = __float2half_rn(w10), h11 = __float2half_rn(w11);
                whi[kt][2 * hf + 0] = (uint32_t)__half_as_ushort(h00) |
                                      ((uint32_t)__half_as_ushort(h01) << 16);
                whi[kt][2 * hf + 1] = (uint32_t)__half_as_ushort(h10) |
                                      ((uint32_t)__half_as_ushort(h11) << 16);
                wlo[kt][2 * hf + 0] = packh2(w00 - __half2float(h00),
                                             w01 - __half2float(h01));
                wlo[kt][2 * hf + 1] = packh2(w10 - __half2float(h10),
                                             w11 - __half2float(h11));
            }
        }
    }

    // ============ GEMM2: mod[64,256] = W . (a*V), two 128-col V chunks ============
    const uint32_t vOff = (uint32_t)(lane & 15) * ROWB + (uint32_t)(lane >> 4) * 16u;

    #pragma unroll 1
    for (int j = 0; j < 2; ++j) {
        if (j > 0) __syncthreads();   // previous GEMM2 chunk done reading V buffer

        // ---- cp.async V chunk (a already folded in prelude) ----
        {
            const __half* vs = g_Vf + (size_t)pair * (R_ * D_) + j * 128;
            #pragma unroll
            for (int g = 0; g < 8; ++g) {
                const int idx = g * 128 + tid;
                const int r = idx >> 4, gc = idx & 15;
                cpa16(smb + SMO_BB + (uint32_t)r * ROWB + (uint32_t)gc * 16u,
                      vs + (size_t)r * D_ + gc * 8);
            }
            asm volatile("cp.async.commit_group;" ::: "memory");
            asm volatile("cp.async.wait_group 0;" ::: "memory");
        }
        __syncthreads();

        #pragma unroll 1
        for (int sub = 0; sub < 2; ++sub) {     // 64 output cols at a time
            float acc2[8][4];
            #pragma unroll
            for (int nt = 0; nt < 8; ++nt)
                #pragma unroll
                for (int i = 0; i < 4; ++i) acc2[nt][i] = 0.f;

            #pragma unroll
            for (int k = 0; k < 4; ++k) {
                #pragma unroll
                for (int g = 0; g < 4; ++g) {
                    uint32_t bb[4];
                    ldsm4t(bb, smb + SMO_BB + vOff + (uint32_t)k * (16u * ROWB) +
                               (uint32_t)sub * 128u + (uint32_t)g * 32u);
                    mma16816(acc2[2 * g + 0], whi[k], bb + 0);
                    mma16816(acc2[2 * g + 1], whi[k], bb + 2);
                    mma16816(acc2[2 * g + 0], wlo[k], bb + 0);
                    mma16816(acc2[2 * g + 1], wlo[k], bb + 2);
                }
            }

            // ---- Epilogue2: out = q * mod (q re-read from gmem, L2-resident) ----
            #pragma unroll
            for (int h = 0; h < 2; ++h) {
                const int m = 16 * wid + (lane >> 2) + 8 * h;
                const size_t gbase = ((size_t)(s * N_ + n0 + m) * B_ + b) * D_;
                #pragma unroll
                for (int nt = 0; nt < 8; ++nt) {
                    const int col = 128 * j + 64 * sub + 8 * nt + 2 * (lane & 3);
                    float2 qv = *(const float2*)(q + gbase + col);
                    float2 o;
                    o.x = qv.x * acc2[nt][2 * h];
                    o.y = qv.y * acc2[nt][2 * h + 1];
                    *(float2*)(out + gbase + col) = o;
                }
            }
        }
    }
}

extern "C" void kernel_launch(void* const* d_in, const int* in_sizes, int n_in,
                              void* d_out, int out_size)
{
    const float* q    = (const float*)d_in[0];
    const float* pm_K = (const float*)d_in[1];
    const float* pm_V = (const float*)d_in[2];
    const float* pm_a = (const float*)d_in[3];
    float* out = (float*)d_out;

    cudaFuncSetAttribute(ProceduralMemory_81535659147884_kernel,
                         cudaFuncAttributeMaxDynamicSharedMemorySize, SMEM_TOTAL);

    // Prelude: convert K -> fp16, a*V -> fp16 into device scratch (~2us)
    ProceduralMemory_81535659147884_cvt<<<KV_ELEMS / 512, 256>>>(pm_K, pm_V, pm_a);

    dim3 grid(BS_ * B_ * (N_ / MTILE));   // 4096 CTAs
    ProceduralMemory_81535659147884_kernel<<<grid, THREADS, SMEM_TOTAL>>>(q, out);
}

// round 9
// speedup vs baseline: 2.0921x; 1.0294x over previous
#include <cuda_runtime.h>
#include <cuda_fp16.h>
#include <cstdint>

#define BS_  8
#define N_   4096
#define B_   8
#define R_   64
#define D_   256

#define MTILE   64
#define THREADS 128
#define ROWB    272        // bytes per smem row: 136 fp16 (128 data + 8 pad)

#define KV_ELEMS (BS_*B_*R_*D_)   // 1,048,576

// ---- smem layout (bytes) ----
#define SMO_AHI  0                      // q chunk hi  [64][136] fp16 = 17408 (later V0)
#define SMO_ALO  17408                  // q chunk lo                  (later V0)
#define SMO_BB   34816                  // K chunk fp16 [64][136]      (later V1)
#define SMO_PART 52224                  // 128 floats: ssq partials [64][2]
#define SMO_INV  52736                  // 64 floats
#define SMEM_TOTAL 53248

// Pre-converted K and a*V (fp16), written by the prelude kernel.
__device__ __half g_Kf[KV_ELEMS];
__device__ __half g_Vf[KV_ELEMS];

__global__ __launch_bounds__(256)
void ProceduralMemory_81535659147884_cvt(const float* __restrict__ K,
                                         const float* __restrict__ V,
                                         const float* __restrict__ a)
{
    const int idx = blockIdx.x * 256 + threadIdx.x;      // per float2
    const float2 k2 = ((const float2*)K)[idx];
    const float2 v2 = ((const float2*)V)[idx];
    const float av = a[idx / (D_ / 2)];
    ((__half2*)g_Kf)[idx] = __floats2half2_rn(k2.x, k2.y);
    ((__half2*)g_Vf)[idx] = __floats2half2_rn(v2.x * av, v2.y * av);
}

__device__ __forceinline__ uint32_t smem_u32(const void* p) {
    uint32_t a;
    asm("{ .reg .u64 t; cvta.to.shared.u64 t, %1; cvt.u32.u64 %0, t; }" : "=r"(a) : "l"(p));
    return a;
}
__device__ __forceinline__ void cpa16(uint32_t dst, const void* src) {
    asm volatile("cp.async.cg.shared.global [%0], [%1], 16;" :: "r"(dst), "l"(src));
}
__device__ __forceinline__ void ldsm4(uint32_t* r, uint32_t addr) {
    asm volatile("ldmatrix.sync.aligned.m8n8.x4.shared.b16 {%0,%1,%2,%3}, [%4];"
                 : "=r"(r[0]), "=r"(r[1]), "=r"(r[2]), "=r"(r[3]) : "r"(addr));
}
__device__ __forceinline__ void ldsm4t(uint32_t* r, uint32_t addr) {
    asm volatile("ldmatrix.sync.aligned.m8n8.x4.trans.shared.b16 {%0,%1,%2,%3}, [%4];"
                 : "=r"(r[0]), "=r"(r[1]), "=r"(r[2]), "=r"(r[3]) : "r"(addr));
}
__device__ __forceinline__ void mma16816(float* c, const uint32_t* a, const uint32_t* b) {
    asm volatile("mma.sync.aligned.m16n8k16.row.col.f32.f16.f16.f32 "
                 "{%0,%1,%2,%3}, {%4,%5,%6,%7}, {%8,%9}, {%0,%1,%2,%3};"
                 : "+f"(c[0]), "+f"(c[1]), "+f"(c[2]), "+f"(c[3])
                 : "r"(a[0]), "r"(a[1]), "r"(a[2]), "r"(a[3]), "r"(b[0]), "r"(b[1]));
}
__device__ __forceinline__ uint32_t packh2(float x, float y) {
    __half2 h = __floats2half2_rn(x, y);
    return *(uint32_t*)&h;
}
// split float4 into fp16 hi + fp16 residual lo
__device__ __forceinline__ void split4h(float4 v, uint2& hi, uint2& lo) {
    __half hx = __float2half_rn(v.x), hy = __float2half_rn(v.y);
    __half hz = __float2half_rn(v.z), hw = __float2half_rn(v.w);
    hi.x = (uint32_t)__half_as_ushort(hx) | ((uint32_t)__half_as_ushort(hy) << 16);
    hi.y = (uint32_t)__half_as_ushort(hz) | ((uint32_t)__half_as_ushort(hw) << 16);
    lo.x = packh2(v.x - __half2float(hx), v.y - __half2float(hy));
    lo.y = packh2(v.z - __half2float(hz), v.w - __half2float(hw));
}

__global__ __launch_bounds__(THREADS, 4)
void ProceduralMemory_81535659147884_kernel(
    const float* __restrict__ q,
    float* __restrict__ out)
{
    extern __shared__ char smc[];
    const uint32_t smb = smem_u32(smc);

    const int tid  = threadIdx.x;
    const int wid  = tid >> 5;        // 0..3
    const int lane = tid & 31;

    const int pair = blockIdx.x >> 6;          // 0..63
    const int tile = blockIdx.x & 63;          // 0..63
    const int s = pair >> 3, b = pair & 7;
    const int n0 = tile * MTILE;

    float* partS = (float*)(smc + SMO_PART);
    float* invS  = (float*)(smc + SMO_INV);

    // GEMM1 accumulators: warp tile 16 rows x 64 n, persist over 2 K-chunks
    float acc[8][4];
    #pragma unroll
    for (int nt = 0; nt < 8; ++nt)
        #pragma unroll
        for (int i = 0; i < 4; ++i) acc[nt][i] = 0.f;

    const uint32_t aOff = (uint32_t)(16 * wid + (lane & 15)) * ROWB +
                          (uint32_t)(lane >> 4) * 16u;
    const uint32_t bOff = (uint32_t)((lane & 7) + ((lane & 16) >> 1)) * ROWB +
                          (uint32_t)((lane >> 3) & 1) * 16u;

    #pragma unroll 1
    for (int c = 0; c < 2; ++c) {
        if (c > 0) __syncthreads();   // GEMM1 chunk0 done reading buffers

        // ---- Issue K chunk cp.async first (flies under the q work below) ----
        {
            const __half* ks = g_Kf + (size_t)pair * (R_ * D_) + c * 128;
            #pragma unroll
            for (int g = 0; g < 8; ++g) {
                const int idx = g * 128 + tid;        // 0..1023
                const int r = idx >> 4, gc = idx & 15;
                cpa16(smb + SMO_BB + (uint32_t)r * ROWB + (uint32_t)gc * 16u,
                      ks + (size_t)r * D_ + gc * 8);
            }
            asm volatile("cp.async.commit_group;" ::: "memory");
        }

        // ---- Load + split q chunk [64 rows, cols 128c..] ----
        {
            const float4* qg = (const float4*)q;
            #pragma unroll 4
            for (int rr = 0; rr < 16; ++rr) {
                const int m = 16 * wid + rr;
                float4 v = qg[((size_t)(s * N_ + n0 + m) * B_ + b) * 64 + c * 32 + lane];
                float ss = v.x * v.x + v.y * v.y + v.z * v.z + v.w * v.w;
                #pragma unroll
                for (int o = 16; o; o >>= 1) ss += __shfl_xor_sync(0xFFFFFFFFu, ss, o);
                if (lane == 0) partS[m * 2 + c] = ss;
                uint2 hi, lo; split4h(v, hi, lo);
                uint32_t a1 = (uint32_t)m * ROWB + (uint32_t)lane * 8u;
                *(uint2*)(smc + SMO_AHI + a1) = hi;
                *(uint2*)(smc + SMO_ALO + a1) = lo;
            }
        }
        asm volatile("cp.async.wait_group 0;" ::: "memory");
        __syncthreads();

        if (c == 1 && tid < MTILE)
            invS[tid] = 1.0f / fmaxf(sqrtf(partS[2 * tid] + partS[2 * tid + 1]), 1e-8f);

        // ---- GEMM1 partial: shared-B, 2 A-passes (hi, lo) per k-step ----
        #pragma unroll
        for (int k = 0; k < 8; ++k) {
            uint32_t ah[4], al[4];
            ldsm4(ah, smb + SMO_AHI + aOff + (uint32_t)k * 32u);
            ldsm4(al, smb + SMO_ALO + aOff + (uint32_t)k * 32u);
            #pragma unroll
            for (int g = 0; g < 4; ++g) {
                uint32_t bb[4];
                ldsm4(bb, smb + SMO_BB + bOff + (uint32_t)g * (16u * ROWB) +
                          (uint32_t)k * 32u);
                mma16816(acc[2 * g + 0], ah, bb + 0);
                mma16816(acc[2 * g + 1], ah, bb + 2);
                mma16816(acc[2 * g + 0], al, bb + 0);
                mma16816(acc[2 * g + 1], al, bb + 2);
            }
        }
    }
    __syncthreads();   // GEMM1 done reading ALO/BB; invS visible below

    // ---- Issue BOTH V chunks now: V0 -> ALO, V1 -> BB (two commit groups) ----
    {
        const __half* vs = g_Vf + (size_t)pair * (R_ * D_);
        #pragma unroll
        for (int g = 0; g < 8; ++g) {
            const int idx = g * 128 + tid;
            const int r = idx >> 4, gc = idx & 15;
            cpa16(smb + SMO_ALO + (uint32_t)r * ROWB + (uint32_t)gc * 16u,
                  vs + (size_t)r * D_ + gc * 8);
        }
        asm volatile("cp.async.commit_group;" ::: "memory");
        #pragma unroll
        for (int g = 0; g < 8; ++g) {
            const int idx = g * 128 + tid;
            const int r = idx >> 4, gc = idx & 15;
            cpa16(smb + SMO_BB + (uint32_t)r * ROWB + (uint32_t)gc * 16u,
                  vs + (size_t)r * D_ + 128 + gc * 8);
        }
        asm volatile("cp.async.commit_group;" ::: "memory");
    }

    // ---- Epilogue1 (registers only, overlaps V copies):
    //      w = score * inv -> fp16 hi/lo A-fragments ----
    uint32_t whi[4][4], wlo[4][4];
    {
        const int r0 = 16 * wid + (lane >> 2);
        const float inv0 = invS[r0], inv1 = invS[r0 + 8];
        #pragma unroll
        for (int kt = 0; kt < 4; ++kt) {
            #pragma unroll
            for (int hf = 0; hf < 2; ++hf) {
                const int nt = 2 * kt + hf;
                float w00 = acc[nt][0] * inv0, w01 = acc[nt][1] * inv0;
                float w10 = acc[nt][2] * inv1, w11 = acc[nt][3] * inv1;
                __half h00 = __float2half_rn(w00), h01 = __float2half_rn(w01);
                __half h10 = __float2half_rn(w10), h11 = __float2half_rn(w11);
                whi[kt][2 * hf + 0] = (uint32_t)__half_as_ushort(h00) |
                                      ((uint32_t)__half_as_ushort(h01) << 16);
                whi[kt][2 * hf + 1] = (uint32_t)__half_as_ushort(h10) |
                                      ((uint32_t)__half_as_ushort(h11) << 16);
                wlo[kt][2 * hf + 0] = packh2(w00 - __half2float(h00),
                                             w01 - __half2float(h01));
                wlo[kt][2 * hf + 1] = packh2(w10 - __half2float(h10),
                                             w11 - __half2float(h11));
            }
        }
    }

    // ============ GEMM2: mod[64,256] = W . (a*V); V0 in ALO, V1 in BB ============
    const uint32_t vOff = (uint32_t)(lane & 15) * ROWB + (uint32_t)(lane >> 4) * 16u;

    #pragma unroll 1
    for (int j = 0; j < 2; ++j) {
        if (j == 0) {
            asm volatile("cp.async.wait_group 1;" ::: "memory");  // V0 landed
        } else {
            asm volatile("cp.async.wait_group 0;" ::: "memory");  // V1 landed
        }
        __syncthreads();   // cross-thread visibility of the V chunk

        const uint32_t vBase = smb + (j == 0 ? SMO_ALO : SMO_BB) + vOff;

        #pragma unroll 1
        for (int sub = 0; sub < 2; ++sub) {     // 64 output cols at a time
            float acc2[8][4];
            #pragma unroll
            for (int nt = 0; nt < 8; ++nt)
                #pragma unroll
                for (int i = 0; i < 4; ++i) acc2[nt][i] = 0.f;

            #pragma unroll
            for (int k = 0; k < 4; ++k) {
                #pragma unroll
                for (int g = 0; g < 4; ++g) {
                    uint32_t bb[4];
                    ldsm4t(bb, vBase + (uint32_t)k * (16u * ROWB) +
                               (uint32_t)sub * 128u + (uint32_t)g * 32u);
                    mma16816(acc2[2 * g + 0], whi[k], bb + 0);
                    mma16816(acc2[2 * g + 1], whi[k], bb + 2);
                    mma16816(acc2[2 * g + 0], wlo[k], bb + 0);
                    mma16816(acc2[2 * g + 1], wlo[k], bb + 2);
                }
            }

            // ---- Epilogue2: out = q * mod (q re-read from gmem, L2-resident) ----
            #pragma unroll
            for (int h = 0; h < 2; ++h) {
                const int m = 16 * wid + (lane >> 2) + 8 * h;
                const size_t gbase = ((size_t)(s * N_ + n0 + m) * B_ + b) * D_;
                #pragma unroll
                for (int nt = 0; nt < 8; ++nt) {
                    const int col = 128 * j + 64 * sub + 8 * nt + 2 * (lane & 3);
                    float2 qv = *(const float2*)(q + gbase + col);
                    float2 o;
                    o.x = qv.x * acc2[nt][2 * h];
                    o.y = qv.y * acc2[nt][2 * h + 1];
                    *(float2*)(out + gbase + col) = o;
                }
            }
        }
    }
}

extern "C" void kernel_launch(void* const* d_in, const int* in_sizes, int n_in,
                              void* d_out, int out_size)
{
    const float* q    = (const float*)d_in[0];
    const float* pm_K = (const float*)d_in[1];
    const float* pm_V = (const float*)d_in[2];
    const float* pm_a = (const float*)d_in[3];
    float* out = (float*)d_out;

    cudaFuncSetAttribute(ProceduralMemory_81535659147884_kernel,
                         cudaFuncAttributeMaxDynamicSharedMemorySize, SMEM_TOTAL);

    // Prelude: convert K -> fp16, a*V -> fp16 into device scratch (~2us)
    ProceduralMemory_81535659147884_cvt<<<KV_ELEMS / 512, 256>>>(pm_K, pm_V, pm_a);

    dim3 grid(BS_ * B_ * (N_ / MTILE));   // 4096 CTAs
    ProceduralMemory_81535659147884_kernel<<<grid, THREADS, SMEM_TOTAL>>>(q, out);
}

// round 10
// speedup vs baseline: 2.2645x; 1.0824x over previous
#include <cuda_runtime.h>
#include <cuda_fp16.h>
#include <cstdint>

#define BS_  8
#define N_   4096
#define B_   8
#define R_   64
#define D_   256

#define MTILE   64
#define THREADS 128
#define ROWB    272        // bytes per smem row: 136 fp16 (128 data + 8 pad)

#define KV_ELEMS (BS_*B_*R_*D_)   // 1,048,576

// ---- smem layout (bytes) ----
#define SMO_AHI  0                      // q chunk fp16 [64][136] = 17408 (later V0)
#define SMO_BB   17408                  // K chunk fp16 [64][136]         (later V1)
#define SMO_PART 34816                  // 128 floats: ssq partials [64][2]
#define SMO_INV  35328                  // 64 floats
#define SMEM_TOTAL 35584

// Pre-converted K and a*V (fp16), written by the prelude kernel.
__device__ __half g_Kf[KV_ELEMS];
__device__ __half g_Vf[KV_ELEMS];

__global__ __launch_bounds__(256)
void ProceduralMemory_81535659147884_cvt(const float* __restrict__ K,
                                         const float* __restrict__ V,
                                         const float* __restrict__ a)
{
    const int idx = blockIdx.x * 256 + threadIdx.x;      // per float2
    const float2 k2 = ((const float2*)K)[idx];
    const float2 v2 = ((const float2*)V)[idx];
    const float av = a[idx / (D_ / 2)];
    ((__half2*)g_Kf)[idx] = __floats2half2_rn(k2.x, k2.y);
    ((__half2*)g_Vf)[idx] = __floats2half2_rn(v2.x * av, v2.y * av);
}

__device__ __forceinline__ uint32_t smem_u32(const void* p) {
    uint32_t a;
    asm("{ .reg .u64 t; cvta.to.shared.u64 t, %1; cvt.u32.u64 %0, t; }" : "=r"(a) : "l"(p));
    return a;
}
__device__ __forceinline__ void cpa16(uint32_t dst, const void* src) {
    asm volatile("cp.async.cg.shared.global [%0], [%1], 16;" :: "r"(dst), "l"(src));
}
__device__ __forceinline__ void ldsm4(uint32_t* r, uint32_t addr) {
    asm volatile("ldmatrix.sync.aligned.m8n8.x4.shared.b16 {%0,%1,%2,%3}, [%4];"
                 : "=r"(r[0]), "=r"(r[1]), "=r"(r[2]), "=r"(r[3]) : "r"(addr));
}
__device__ __forceinline__ void ldsm4t(uint32_t* r, uint32_t addr) {
    asm volatile("ldmatrix.sync.aligned.m8n8.x4.trans.shared.b16 {%0,%1,%2,%3}, [%4];"
                 : "=r"(r[0]), "=r"(r[1]), "=r"(r[2]), "=r"(r[3]) : "r"(addr));
}
__device__ __forceinline__ void mma16816(float* c, const uint32_t* a, const uint32_t* b) {
    asm volatile("mma.sync.aligned.m16n8k16.row.col.f32.f16.f16.f32 "
                 "{%0,%1,%2,%3}, {%4,%5,%6,%7}, {%8,%9}, {%0,%1,%2,%3};"
                 : "+f"(c[0]), "+f"(c[1]), "+f"(c[2]), "+f"(c[3])
                 : "r"(a[0]), "r"(a[1]), "r"(a[2]), "r"(a[3]), "r"(b[0]), "r"(b[1]));
}
__device__ __forceinline__ uint32_t packh2(float x, float y) {
    __half2 h = __floats2half2_rn(x, y);
    return *(uint32_t*)&h;
}
__device__ __forceinline__ void cvt4h(float4 v, uint2& hi) {
    __half hx = __float2half_rn(v.x), hy = __float2half_rn(v.y);
    __half hz = __float2half_rn(v.z), hw = __float2half_rn(v.w);
    hi.x = (uint32_t)__half_as_ushort(hx) | ((uint32_t)__half_as_ushort(hy) << 16);
    hi.y = (uint32_t)__half_as_ushort(hz) | ((uint32_t)__half_as_ushort(hw) << 16);
}

__global__ __launch_bounds__(THREADS, 5)
void ProceduralMemory_81535659147884_kernel(
    const float* __restrict__ q,
    float* __restrict__ out)
{
    extern __shared__ char smc[];
    const uint32_t smb = smem_u32(smc);

    const int tid  = threadIdx.x;
    const int wid  = tid >> 5;        // 0..3
    const int lane = tid & 31;

    const int pair = blockIdx.x >> 6;          // 0..63
    const int tile = blockIdx.x & 63;          // 0..63
    const int s = pair >> 3, b = pair & 7;
    const int n0 = tile * MTILE;

    float* partS = (float*)(smc + SMO_PART);
    float* invS  = (float*)(smc + SMO_INV);

    // GEMM1 accumulators: warp tile 16 rows x 64 n, persist over 2 K-chunks
    float acc[8][4];
    #pragma unroll
    for (int nt = 0; nt < 8; ++nt)
        #pragma unroll
        for (int i = 0; i < 4; ++i) acc[nt][i] = 0.f;

    const uint32_t aOff = (uint32_t)(16 * wid + (lane & 15)) * ROWB +
                          (uint32_t)(lane >> 4) * 16u;
    const uint32_t bOff = (uint32_t)((lane & 7) + ((lane & 16) >> 1)) * ROWB +
                          (uint32_t)((lane >> 3) & 1) * 16u;

    #pragma unroll 1
    for (int c = 0; c < 2; ++c) {
        if (c > 0) __syncthreads();   // GEMM1 chunk0 done reading buffers

        // ---- Issue K chunk cp.async first (flies under the q work below) ----
        {
            const __half* ks = g_Kf + (size_t)pair * (R_ * D_) + c * 128;
            #pragma unroll
            for (int g = 0; g < 8; ++g) {
                const int idx = g * 128 + tid;        // 0..1023
                const int r = idx >> 4, gc = idx & 15;
                cpa16(smb + SMO_BB + (uint32_t)r * ROWB + (uint32_t)gc * 16u,
                      ks + (size_t)r * D_ + gc * 8);
            }
            asm volatile("cp.async.commit_group;" ::: "memory");
        }

        // ---- Load q chunk [64 rows, cols 128c..], cvt fp16, ssq partials ----
        {
            const float4* qg = (const float4*)q;
            #pragma unroll 4
            for (int rr = 0; rr < 16; ++rr) {
                const int m = 16 * wid + rr;
                float4 v = qg[((size_t)(s * N_ + n0 + m) * B_ + b) * 64 + c * 32 + lane];
                float ss = v.x * v.x + v.y * v.y + v.z * v.z + v.w * v.w;
                #pragma unroll
                for (int o = 16; o; o >>= 1) ss += __shfl_xor_sync(0xFFFFFFFFu, ss, o);
                if (lane == 0) partS[m * 2 + c] = ss;
                uint2 hi; cvt4h(v, hi);
                *(uint2*)(smc + SMO_AHI + (uint32_t)m * ROWB + (uint32_t)lane * 8u) = hi;
            }
        }
        asm volatile("cp.async.wait_group 0;" ::: "memory");
        __syncthreads();

        if (c == 1 && tid < MTILE)
            invS[tid] = 1.0f / fmaxf(sqrtf(partS[2 * tid] + partS[2 * tid + 1]), 1e-8f);

        // ---- GEMM1 partial: pure fp16, 1 pass per k-step ----
        #pragma unroll
        for (int k = 0; k < 8; ++k) {
            uint32_t ah[4];
            ldsm4(ah, smb + SMO_AHI + aOff + (uint32_t)k * 32u);
            #pragma unroll
            for (int g = 0; g < 4; ++g) {
                uint32_t bb[4];
                ldsm4(bb, smb + SMO_BB + bOff + (uint32_t)g * (16u * ROWB) +
                          (uint32_t)k * 32u);
                mma16816(acc[2 * g + 0], ah, bb + 0);
                mma16816(acc[2 * g + 1], ah, bb + 2);
            }
        }
    }
    __syncthreads();   // GEMM1 done reading AHI/BB; invS visible below

    // ---- Issue BOTH V chunks now: V0 -> AHI, V1 -> BB (two commit groups) ----
    {
        const __half* vs = g_Vf + (size_t)pair * (R_ * D_);
        #pragma unroll
        for (int g = 0; g < 8; ++g) {
            const int idx = g * 128 + tid;
            const int r = idx >> 4, gc = idx & 15;
            cpa16(smb + SMO_AHI + (uint32_t)r * ROWB + (uint32_t)gc * 16u,
                  vs + (size_t)r * D_ + gc * 8);
        }
        asm volatile("cp.async.commit_group;" ::: "memory");
        #pragma unroll
        for (int g = 0; g < 8; ++g) {
            const int idx = g * 128 + tid;
            const int r = idx >> 4, gc = idx & 15;
            cpa16(smb + SMO_BB + (uint32_t)r * ROWB + (uint32_t)gc * 16u,
                  vs + (size_t)r * D_ + 128 + gc * 8);
        }
        asm volatile("cp.async.commit_group;" ::: "memory");
    }

    // ---- Epilogue1 (registers only, overlaps V copies):
    //      w = score * inv -> fp16 A-fragments ----
    uint32_t whi[4][4];
    {
        const int r0 = 16 * wid + (lane >> 2);
        const float inv0 = invS[r0], inv1 = invS[r0 + 8];
        #pragma unroll
        for (int kt = 0; kt < 4; ++kt) {
            #pragma unroll
            for (int hf = 0; hf < 2; ++hf) {
                const int nt = 2 * kt + hf;
                whi[kt][2 * hf + 0] = packh2(acc[nt][0] * inv0, acc[nt][1] * inv0);
                whi[kt][2 * hf + 1] = packh2(acc[nt][2] * inv1, acc[nt][3] * inv1);
            }
        }
    }

    // ============ GEMM2: mod[64,256] = W . (a*V); V0 in AHI, V1 in BB ============
    const uint32_t vOff = (uint32_t)(lane & 15) * ROWB + (uint32_t)(lane >> 4) * 16u;

    #pragma unroll 1
    for (int j = 0; j < 2; ++j) {
        if (j == 0) {
            asm volatile("cp.async.wait_group 1;" ::: "memory");  // V0 landed
        } else {
            asm volatile("cp.async.wait_group 0;" ::: "memory");  // V1 landed
        }
        __syncthreads();   // cross-thread visibility of the V chunk

        const uint32_t vBase = smb + (j == 0 ? SMO_AHI : SMO_BB) + vOff;

        #pragma unroll 1
        for (int sub = 0; sub < 2; ++sub) {     // 64 output cols at a time
            float acc2[8][4];
            #pragma unroll
            for (int nt = 0; nt < 8; ++nt)
                #pragma unroll
                for (int i = 0; i < 4; ++i) acc2[nt][i] = 0.f;

            #pragma unroll
            for (int k = 0; k < 4; ++k) {
                #pragma unroll
                for (int g = 0; g < 4; ++g) {
                    uint32_t bb[4];
                    ldsm4t(bb, vBase + (uint32_t)k * (16u * ROWB) +
                               (uint32_t)sub * 128u + (uint32_t)g * 32u);
                    mma16816(acc2[2 * g + 0], whi[k], bb + 0);
                    mma16816(acc2[2 * g + 1], whi[k], bb + 2);
                }
            }

            // ---- Epilogue2: out = q * mod (q re-read from gmem, L2-resident) ----
            #pragma unroll
            for (int h = 0; h < 2; ++h) {
                const int m = 16 * wid + (lane >> 2) + 8 * h;
                const size_t gbase = ((size_t)(s * N_ + n0 + m) * B_ + b) * D_;
                #pragma unroll
                for (int nt = 0; nt < 8; ++nt) {
                    const int col = 128 * j + 64 * sub + 8 * nt + 2 * (lane & 3);
                    float2 qv = *(const float2*)(q + gbase + col);
                    float2 o;
                    o.x = qv.x * acc2[nt][2 * h];
                    o.y = qv.y * acc2[nt][2 * h + 1];
                    *(float2*)(out + gbase + col) = o;
                }
            }
        }
    }
}

extern "C" void kernel_launch(void* const* d_in, const int* in_sizes, int n_in,
                              void* d_out, int out_size)
{
    const float* q    = (const float*)d_in[0];
    const float* pm_K = (const float*)d_in[1];
    const float* pm_V = (const float*)d_in[2];
    const float* pm_a = (const float*)d_in[3];
    float* out = (float*)d_out;

    cudaFuncSetAttribute(ProceduralMemory_81535659147884_kernel,
                         cudaFuncAttributeMaxDynamicSharedMemorySize, SMEM_TOTAL);

    // Prelude: convert K -> fp16, a*V -> fp16 into device scratch (~2us)
    ProceduralMemory_81535659147884_cvt<<<KV_ELEMS / 512, 256>>>(pm_K, pm_V, pm_a);

    dim3 grid(BS_ * B_ * (N_ / MTILE));   // 4096 CTAs
    ProceduralMemory_81535659147884_kernel<<<grid, THREADS, SMEM_TOTAL>>>(q, out);
}